// round 14
// baseline (speedup 1.0000x reference)
#include <cuda_runtime.h>
#include <cuda_bf16.h>
#include <math.h>
#include <stdint.h>

// ---------------------------------------------------------------------------
// SemanticConsistencyLoss — R14:
//  accum = R13 access patterns, re-pipelined: 4 tile buffers, loop unrolled x4,
//          ONE barrier per 2 tiles (was 1/tile), prefetch issued before RMW.
//  reduce = grid (150 cls, 2 ch-halves), 19-chunk chains, ticket -> norm.
// ---------------------------------------------------------------------------

#define NUM_CLASSES 150
#define CH        256
#define HCH       128
#define NPIX      (512 * 512)
#define CHUNKS    74
#define PPC       3584            // 74*3584 >= NPIX; PPC/32 = 112 (div by 4)
#define TPX       32
#define TPB       512
#define TSTRIDE   33
#define TILE_W    (HCH * TSTRIDE) // 4224 words per buffer

__device__ float g_psums[2][CHUNKS][NUM_CLASSES][CH];
__device__ float g_pcnts[2][CHUNKS][NUM_CLASSES];
__device__ float g_csq2[NUM_CLASSES * 2];
__device__ unsigned int g_ticket = 0;

// smem floats: tile[4][4224] | lbl[3584] | cnt[152]
#define SM_LBL      (4 * TILE_W)
#define SM_CNT      (SM_LBL + PPC)
#define SMEM_FLOATS (SM_CNT + 152)
#define SMEM_BYTES  (SMEM_FLOATS * 4)   // ~82.5 KB -> occ 2

#define ACC_CASE(k)                                                        \
    case k: acc[k].x += v0; acc[k].y += v1; acc[k].z += v2; acc[k].w += v3; break;

// prefetch tile T into r + label reg L (patterns identical to R13)
#define PF(T, L) do {                                                      \
    const int _p0 = pbase + (T) * TPX;                                     \
    _Pragma("unroll")                                                      \
    for (int i = 0; i < 2; ++i) {                                          \
        int q = tid + TPB * i;                                             \
        int ch = q >> 3, p4 = q & 7;                                       \
        r[i] = *(const float4*)(F + (size_t)ch * NPIX + _p0 + p4 * 4);     \
    }                                                                      \
    L = lbl_s[(T) * TPX + lane];                                           \
} while (0)

// stage r into buffer B (compile-time): bank-perfect scalar stores
#define ST(B) do {                                                         \
    float* _tb = tiles + (B) * TILE_W;                                     \
    _Pragma("unroll")                                                      \
    for (int i = 0; i < 2; ++i) {                                          \
        int q = tid + TPB * i;                                             \
        int ch = q >> 3, p4 = q & 7;                                       \
        float* d = _tb + ch * TSTRIDE + p4 * 4;                            \
        d[0] = r[i].x; d[1] = r[i].y; d[2] = r[i].z; d[3] = r[i].w;        \
    }                                                                      \
} while (0)

// RMW buffer B with labels L (identical inner loop to R13)
#define RMWT(B, L) do {                                                    \
    const int lblcur = (L);                                                \
    unsigned m = __ballot_sync(0xffffffffu, (lblcur & 15) == wid);         \
    const float* _tb = tiles + (B) * TILE_W;                               \
    while (m) {                                                            \
        const int j = __ffs(m) - 1;                                        \
        m &= m - 1;                                                        \
        const int row = __shfl_sync(0xffffffffu, lblcur, j);               \
        const float* srcc = _tb + lane * TSTRIDE + j;                      \
        const float v0 = srcc[0];                                          \
        const float v1 = srcc[32 * TSTRIDE];                               \
        const float v2 = srcc[64 * TSTRIDE];                               \
        const float v3 = srcc[96 * TSTRIDE];                               \
        switch (row >> 4) {                                                \
            ACC_CASE(0) ACC_CASE(1) ACC_CASE(2) ACC_CASE(3) ACC_CASE(4)    \
            ACC_CASE(5) ACC_CASE(6) ACC_CASE(7) ACC_CASE(8) ACC_CASE(9)    \
        }                                                                  \
    }                                                                      \
} while (0)

__global__ void __launch_bounds__(TPB, 2)
accum_kernel(const float* __restrict__ src, const float* __restrict__ trg,
             const int* __restrict__ slab, const int* __restrict__ tlab) {
    extern __shared__ float smf[];
    float* tiles = smf;                 // [4][128][33]
    int*   lbl_s = (int*)(smf + SM_LBL);
    int*   cnt   = (int*)(smf + SM_CNT);

    const int chunk = blockIdx.x;
    const int tsel  = blockIdx.y;
    const int chalf = blockIdx.z;
    const float* __restrict__ F =
        (tsel ? trg : src) + (size_t)chalf * HCH * NPIX;
    const int*   __restrict__ L = tsel ? tlab : slab;

    const int tid  = threadIdx.x;
    const int wid  = tid >> 5;          // owns labels lab&15 == wid
    const int lane = tid & 31;

    if (tid < NUM_CLASSES) cnt[tid] = 0;
    __syncthreads();

    const int pbase  = chunk * PPC;
    const int psz    = min(PPC, NPIX - pbase);
    const int ntiles = psz / TPX;       // 112 or 16 (divisible by 4)

    // ---- cache labels in smem + histogram (integer-exact) ----
    for (int i = tid; i < psz; i += TPB) {
        int l = L[pbase + i];
        lbl_s[i] = l;
        if (chalf == 0) atomicAdd(&cnt[l], 1);
    }
    __syncthreads();

    float4 acc[10];
#pragma unroll
    for (int k = 0; k < 10; ++k) acc[k] = make_float4(0.f, 0.f, 0.f, 0.f);

    float4 r[2];
    int lA, lB, lC, lD;

    // ---- prologue: stage tiles 0,1 ----
    PF(0, lA); ST(0);
    PF(1, lB); ST(1);
    __syncthreads();

    for (int t = 0; t < ntiles; t += 4) {
        // ---- phase 1: RMW t,t+1 (buf 0,1); stage t+2,t+3 (buf 2,3) ----
        PF(t + 2, lC);      // LDG issued before RMW: latency hidden
        RMWT(0, lA);
        ST(2);
        PF(t + 3, lD);
        RMWT(1, lB);
        ST(3);
        __syncthreads();

        // ---- phase 2: RMW t+2,t+3 (buf 2,3); stage t+4,t+5 (buf 0,1) ----
        const bool g = (t + 4 < ntiles);
        if (g) PF(t + 4, lA);
        RMWT(2, lC);
        if (g) { ST(0); PF(t + 5, lB); }
        RMWT(3, lD);
        if (g) ST(1);
        __syncthreads();
    }

    // ---- epilogue: registers -> partial scratch (coalesced per lane) ----
    const int nk = (wid < 6) ? 10 : 9;   // classes 16k+wid <= 149
#pragma unroll
    for (int k = 0; k < 10; ++k) {
        if (k < nk) {
            const int cls = 16 * k + wid;
            float* o = &g_psums[tsel][chunk][cls][chalf * HCH];
            o[lane]      = acc[k].x;
            o[lane + 32] = acc[k].y;
            o[lane + 64] = acc[k].z;
            o[lane + 96] = acc[k].w;
        }
    }
    if (chalf == 0 && tid < NUM_CLASSES)
        g_pcnts[tsel][chunk][tid] = (float)cnt[tid];
}

// ---- tail: grid (150, 2 ch-halves), block 1024 ----
// part = tid>>7 (0..7): tsel = part&1, chunk-quarter = part>>1 (19/19/19/17).
__global__ void __launch_bounds__(1024, 1)
reduce_kernel(float* out) {
    const int cls  = blockIdx.x;
    const int half = blockIdx.y;
    const int tid  = threadIdx.x;
    const int chl  = tid & 127;
    const int part = tid >> 7;          // 0..7
    const int tsel = part & 1;
    const int qt   = part >> 1;         // 0..3
    const int ch   = half * 128 + chl;

    const int c0 = qt * 19;
    const int c1 = min(CHUNKS, c0 + 19);

    float s = 0.0f;
#pragma unroll 19
    for (int k = c0; k < c1; ++k)
        s += g_psums[tsel][k][cls][ch];

    __shared__ float sp[8][128];
    sp[part][chl] = s;

    // counts: 148 parallel loads, dual shared-tree (deterministic)
    __shared__ float c0s[128], c1s[128];
    if (tid < 256) {
        const int a = tid >> 7;
        const int i = tid & 127;
        (a ? c1s : c0s)[i] = (i < CHUNKS) ? g_pcnts[a][i][cls] : 0.0f;
    }
    __syncthreads();
#pragma unroll
    for (int st = 64; st > 0; st >>= 1) {
        if (tid < 256) {
            const int a = tid >> 7;
            const int i = tid & 127;
            if (i < st) {
                float* arr = a ? c1s : c0s;
                arr[i] += arr[i + st];
            }
        }
        __syncthreads();
    }

    __shared__ float red[128];
    if (tid < 128) {
        const float ssum = sp[0][tid] + sp[2][tid] + sp[4][tid] + sp[6][tid];
        const float tsum = sp[1][tid] + sp[3][tid] + sp[5][tid] + sp[7][tid];
        const float d = ssum / (c0s[0] + 1e-8f) - tsum / (c1s[0] + 1e-8f);
        red[tid] = d * d;
    }
    __syncthreads();
#pragma unroll
    for (int st = 64; st > 0; st >>= 1) {
        if (tid < st) red[tid] += red[tid + st];
        __syncthreads();
    }

    __shared__ unsigned int is_last;
    if (tid == 0) {
        g_csq2[cls * 2 + half] = red[0];
        __threadfence();
        unsigned int tk = atomicAdd(&g_ticket, 1u);
        is_last = (tk == 2u * NUM_CLASSES - 1u) ? 1u : 0u;
    }
    __syncthreads();

    if (is_last && tid < 32) {
        float s2 = 0.0f;
#pragma unroll
        for (int i = tid; i < 2 * NUM_CLASSES; i += 32)
            s2 += __ldcg(&g_csq2[i]);
#pragma unroll
        for (int o = 16; o > 0; o >>= 1)
            s2 += __shfl_down_sync(0xffffffffu, s2, o);
        if (tid == 0) {
            out[0] = sqrtf(s2);
            g_ticket = 0;              // reset for next graph replay
        }
    }
}

extern "C" void kernel_launch(void* const* d_in, const int* in_sizes, int n_in,
                              void* d_out, int out_size) {
    const float* src = (const float*)d_in[0];   // src_fea  [1,256,512,512] f32
    const float* trg = (const float*)d_in[1];   // trg_fea
    const int*   sl  = (const int*)d_in[2];     // src_labels [1,512,512] i32
    const int*   tl  = (const int*)d_in[3];     // trg_pseudo_labels
    float* out = (float*)d_out;

    cudaFuncSetAttribute(accum_kernel,
                         cudaFuncAttributeMaxDynamicSharedMemorySize,
                         SMEM_BYTES);

    dim3 grid(CHUNKS, 2, 2);   // 296 CTAs = one wave at occ 2
    accum_kernel<<<grid, TPB, SMEM_BYTES>>>(src, trg, sl, tl);
    reduce_kernel<<<dim3(NUM_CLASSES, 2), 1024>>>(out);
}

// round 15
// speedup vs baseline: 1.0334x; 1.0334x over previous
#include <cuda_runtime.h>
#include <cuda_bf16.h>
#include <math.h>
#include <stdint.h>

// ---------------------------------------------------------------------------
// SemanticConsistencyLoss — R15: accum byte-identical to R13 (measured best);
// reduce = R13 shape (grid 150 x block 1024) with float4 loads:
//   thread (q = channel quad, part = tensor x 8 chunk-slices, stride-8 chunks)
//   -> 9-10 LDG.128 per thread, combine in smem, counts tree, ticket -> norm.
// ---------------------------------------------------------------------------

#define NUM_CLASSES 150
#define CH        256
#define HCH       128
#define NPIX      (512 * 512)
#define CHUNKS    74
#define PPC       3584            // 74*3584 >= NPIX, multiple of 32
#define TPX       32
#define TPB       512
#define TSTRIDE   33
#define TILE_W    (HCH * TSTRIDE) // 4224 words per buffer

__device__ float g_psums[2][CHUNKS][NUM_CLASSES][CH];
__device__ float g_pcnts[2][CHUNKS][NUM_CLASSES];
__device__ float g_csq[NUM_CLASSES];
__device__ unsigned int g_ticket = 0;

// smem floats: tile[2][4224] | lbl[3584] | cnt[152]
#define SM_LBL      (2 * TILE_W)
#define SM_CNT      (SM_LBL + PPC)
#define SMEM_FLOATS (SM_CNT + 152)
#define SMEM_BYTES  (SMEM_FLOATS * 4)   // ~48.7 KB -> occ 2

#define ACC_CASE(k)                                                        \
    case k: acc[k].x += v0; acc[k].y += v1; acc[k].z += v2; acc[k].w += v3; break;

__global__ void __launch_bounds__(TPB, 2)
accum_kernel(const float* __restrict__ src, const float* __restrict__ trg,
             const int* __restrict__ slab, const int* __restrict__ tlab) {
    extern __shared__ float smf[];
    float* tiles = smf;                 // [2][128][33]
    int*   lbl_s = (int*)(smf + SM_LBL);
    int*   cnt   = (int*)(smf + SM_CNT);

    const int chunk = blockIdx.x;
    const int tsel  = blockIdx.y;
    const int chalf = blockIdx.z;
    const float* __restrict__ F =
        (tsel ? trg : src) + (size_t)chalf * HCH * NPIX;
    const int*   __restrict__ L = tsel ? tlab : slab;

    const int tid  = threadIdx.x;
    const int wid  = tid >> 5;          // owns labels lab&15 == wid
    const int lane = tid & 31;

    if (tid < NUM_CLASSES) cnt[tid] = 0;
    __syncthreads();

    const int pbase  = chunk * PPC;
    const int psz    = min(PPC, NPIX - pbase);
    const int ntiles = psz / TPX;       // 112 (last chunk: 16)

    // ---- cache labels in smem + histogram (integer-exact) ----
    for (int i = tid; i < psz; i += TPB) {
        int l = L[pbase + i];
        lbl_s[i] = l;
        if (chalf == 0) atomicAdd(&cnt[l], 1);
    }
    __syncthreads();

    // ---- register accumulators: class 16k+wid, channels lane+{0,32,64,96} ----
    float4 acc[10];
#pragma unroll
    for (int k = 0; k < 10; ++k) acc[k] = make_float4(0.f, 0.f, 0.f, 0.f);

    // ---- register prefetch of tile 0 ----
    float4 r[2];
    int mylbl;
    {
#pragma unroll
        for (int i = 0; i < 2; ++i) {
            int q = tid + TPB * i;
            int ch = q >> 3, p4 = q & 7;
            r[i] = *(const float4*)(F + (size_t)ch * NPIX + pbase + p4 * 4);
        }
        mylbl = lbl_s[lane];
    }

    for (int t = 0; t < ntiles; ++t) {
        float* tb = tiles + (t & 1) * TILE_W;

        // ---- stage: bank-perfect scalar stores ----
#pragma unroll
        for (int i = 0; i < 2; ++i) {
            int q = tid + TPB * i;
            int ch = q >> 3, p4 = q & 7;
            float* d = tb + ch * TSTRIDE + p4 * 4;
            d[0] = r[i].x; d[1] = r[i].y; d[2] = r[i].z; d[3] = r[i].w;
        }
        const int lblcur = mylbl;
        __syncthreads();   // one barrier per tile (double buffer -> safe)

        // ---- prefetch next tile (label from smem: short latency) ----
        if (t + 1 < ntiles) {
            const int p0 = pbase + (t + 1) * TPX;
#pragma unroll
            for (int i = 0; i < 2; ++i) {
                int q = tid + TPB * i;
                int ch = q >> 3, p4 = q & 7;
                r[i] = *(const float4*)(F + (size_t)ch * NPIX + p0 + p4 * 4);
            }
            mylbl = lbl_s[(t + 1) * TPX + lane];
        }

        // ---- accumulate into registers: warp-uniform class switch ----
        unsigned m = __ballot_sync(0xffffffffu, (lblcur & 15) == wid);
        while (m) {
            const int j = __ffs(m) - 1;
            m &= m - 1;
            const int row = __shfl_sync(0xffffffffu, lblcur, j);
            const float* srcc = tb + lane * TSTRIDE + j;   // bank = lane+j
            const float v0 = srcc[0];
            const float v1 = srcc[32 * TSTRIDE];
            const float v2 = srcc[64 * TSTRIDE];
            const float v3 = srcc[96 * TSTRIDE];
            switch (row >> 4) {        // warp-uniform branch
                ACC_CASE(0) ACC_CASE(1) ACC_CASE(2) ACC_CASE(3) ACC_CASE(4)
                ACC_CASE(5) ACC_CASE(6) ACC_CASE(7) ACC_CASE(8) ACC_CASE(9)
            }
        }
    }
    __syncthreads();

    // ---- epilogue: registers -> partial scratch (coalesced per lane) ----
    const int nk = (wid < 6) ? 10 : 9;   // classes 16k+wid <= 149
#pragma unroll
    for (int k = 0; k < 10; ++k) {
        if (k < nk) {
            const int cls = 16 * k + wid;
            float* o = &g_psums[tsel][chunk][cls][chalf * HCH];
            o[lane]      = acc[k].x;
            o[lane + 32] = acc[k].y;
            o[lane + 64] = acc[k].z;
            o[lane + 96] = acc[k].w;
        }
    }
    if (chalf == 0 && tid < NUM_CLASSES)
        g_pcnts[tsel][chunk][tid] = (float)cnt[tid];
}

// ---- single tail kernel: grid 150, block 1024, float4 loads ----
// thread: q = tid&63 (channel quad), part = tid>>6 (0..15):
//   tsel = part&1, ks = part>>1 (chunk slice, stride 8).
__global__ void __launch_bounds__(1024, 1)
reduce_kernel(float* out) {
    const int cls  = blockIdx.x;
    const int tid  = threadIdx.x;
    const int q    = tid & 63;
    const int part = tid >> 6;          // 0..15
    const int tsel = part & 1;
    const int ks   = part >> 1;         // 0..7

    // stride-8 chunk slice: 9-10 independent LDG.128 (order-fixed sum)
    float4 a = make_float4(0.f, 0.f, 0.f, 0.f);
    for (int k = ks; k < CHUNKS; k += 8) {
        const float4 v = *(const float4*)(&g_psums[tsel][k][cls][4 * q]);
        a.x += v.x; a.y += v.y; a.z += v.z; a.w += v.w;
    }

    __shared__ float4 sp[16][64];       // 16 KB
    sp[part][q] = a;

    // counts: 148 parallel loads, dual shared-tree (deterministic)
    __shared__ float c0s[128], c1s[128];
    if (tid < 256) {
        const int aa = tid >> 7;        // 0: c0s, 1: c1s
        const int i  = tid & 127;
        (aa ? c1s : c0s)[i] = (i < CHUNKS) ? g_pcnts[aa][i][cls] : 0.0f;
    }
    __syncthreads();
#pragma unroll
    for (int st = 64; st > 0; st >>= 1) {
        if (tid < 256) {
            const int aa = tid >> 7;
            const int i  = tid & 127;
            if (i < st) {
                float* arr = aa ? c1s : c0s;
                arr[i] += arr[i + st];
            }
        }
        __syncthreads();
    }

    __shared__ float red[64];
    if (tid < 64) {
        float4 ssv = make_float4(0.f, 0.f, 0.f, 0.f);
        float4 tsv = make_float4(0.f, 0.f, 0.f, 0.f);
#pragma unroll
        for (int p = 0; p < 8; ++p) {
            const float4 s0 = sp[2 * p][tid];      // tsel 0
            const float4 s1 = sp[2 * p + 1][tid];  // tsel 1
            ssv.x += s0.x; ssv.y += s0.y; ssv.z += s0.z; ssv.w += s0.w;
            tsv.x += s1.x; tsv.y += s1.y; tsv.z += s1.z; tsv.w += s1.w;
        }
        const float is = 1.0f / (c0s[0] + 1e-8f);
        const float it = 1.0f / (c1s[0] + 1e-8f);
        const float d0 = ssv.x * is - tsv.x * it;
        const float d1 = ssv.y * is - tsv.y * it;
        const float d2 = ssv.z * is - tsv.z * it;
        const float d3 = ssv.w * is - tsv.w * it;
        red[tid] = d0 * d0 + d1 * d1 + d2 * d2 + d3 * d3;
    }
    __syncthreads();
#pragma unroll
    for (int st = 32; st > 0; st >>= 1) {
        if (tid < st) red[tid] += red[tid + st];
        __syncthreads();
    }

    __shared__ unsigned int is_last;
    if (tid == 0) {
        g_csq[cls] = red[0];
        __threadfence();
        unsigned int t = atomicAdd(&g_ticket, 1u);
        is_last = (t == (unsigned)gridDim.x - 1u) ? 1u : 0u;
    }
    __syncthreads();

    if (is_last && tid < 32) {
        float s2 = 0.0f;
#pragma unroll
        for (int i = tid; i < NUM_CLASSES; i += 32)
            s2 += __ldcg(&g_csq[i]);
#pragma unroll
        for (int o = 16; o > 0; o >>= 1)
            s2 += __shfl_down_sync(0xffffffffu, s2, o);
        if (tid == 0) {
            out[0] = sqrtf(s2);
            g_ticket = 0;              // reset for next graph replay
        }
    }
}

extern "C" void kernel_launch(void* const* d_in, const int* in_sizes, int n_in,
                              void* d_out, int out_size) {
    const float* src = (const float*)d_in[0];   // src_fea  [1,256,512,512] f32
    const float* trg = (const float*)d_in[1];   // trg_fea
    const int*   sl  = (const int*)d_in[2];     // src_labels [1,512,512] i32
    const int*   tl  = (const int*)d_in[3];     // trg_pseudo_labels
    float* out = (float*)d_out;

    cudaFuncSetAttribute(accum_kernel,
                         cudaFuncAttributeMaxDynamicSharedMemorySize,
                         SMEM_BYTES);

    dim3 grid(CHUNKS, 2, 2);   // 296 CTAs = one wave at occ 2
    accum_kernel<<<grid, TPB, SMEM_BYTES>>>(src, trg, sl, tl);
    reduce_kernel<<<NUM_CLASSES, 1024>>>(out);
}

// round 16
// speedup vs baseline: 1.1117x; 1.0758x over previous
#include <cuda_runtime.h>
#include <cuda_bf16.h>
#include <math.h>
#include <stdint.h>

// ---------------------------------------------------------------------------
// SemanticConsistencyLoss — R16: accum main loop byte-identical to R13
// (measured best, 5 rounds stable). Scratch round-trip eliminated:
//  * epilogue: 40 coalesced float atomicAdds per thread into
//    g_sums[2][150][256] (307 KB) — replaces the 22.7 MB partial write.
//  * counts: per-CTA smem histogram -> atomicAdd into g_cnt[2][150].
//  * reduce: grid 150 x 256 reads g_sums/g_cnt directly (~300 KB), d^2 tree,
//    ticket block -> norm; then RESETS g_sums/g_cnt/ticket for graph replay.
// ---------------------------------------------------------------------------

#define NUM_CLASSES 150
#define CH        256
#define HCH       128
#define NPIX      (512 * 512)
#define CHUNKS    74
#define PPC       3584            // 74*3584 >= NPIX, multiple of 32
#define TPX       32
#define TPB       512
#define TSTRIDE   33
#define TILE_W    (HCH * TSTRIDE) // 4224 words per buffer

__device__ float g_sums[2][NUM_CLASSES][CH];   // zero-initialized statics
__device__ int   g_cnt[2][NUM_CLASSES];
__device__ float g_csq[NUM_CLASSES];
__device__ unsigned int g_ticket = 0;

// smem floats: tile[2][4224] | lbl[3584] | cnt[152]
#define SM_LBL      (2 * TILE_W)
#define SM_CNT      (SM_LBL + PPC)
#define SMEM_FLOATS (SM_CNT + 152)
#define SMEM_BYTES  (SMEM_FLOATS * 4)   // ~48.7 KB -> occ 2

#define ACC_CASE(k)                                                        \
    case k: acc[k].x += v0; acc[k].y += v1; acc[k].z += v2; acc[k].w += v3; break;

__global__ void __launch_bounds__(TPB, 2)
accum_kernel(const float* __restrict__ src, const float* __restrict__ trg,
             const int* __restrict__ slab, const int* __restrict__ tlab) {
    extern __shared__ float smf[];
    float* tiles = smf;                 // [2][128][33]
    int*   lbl_s = (int*)(smf + SM_LBL);
    int*   cnt   = (int*)(smf + SM_CNT);

    const int chunk = blockIdx.x;
    const int tsel  = blockIdx.y;
    const int chalf = blockIdx.z;
    const float* __restrict__ F =
        (tsel ? trg : src) + (size_t)chalf * HCH * NPIX;
    const int*   __restrict__ L = tsel ? tlab : slab;

    const int tid  = threadIdx.x;
    const int wid  = tid >> 5;          // owns labels lab&15 == wid
    const int lane = tid & 31;

    if (tid < NUM_CLASSES) cnt[tid] = 0;
    __syncthreads();

    const int pbase  = chunk * PPC;
    const int psz    = min(PPC, NPIX - pbase);
    const int ntiles = psz / TPX;       // 112 (last chunk: 16)

    // ---- cache labels in smem + histogram (integer-exact) ----
    for (int i = tid; i < psz; i += TPB) {
        int l = L[pbase + i];
        lbl_s[i] = l;
        if (chalf == 0) atomicAdd(&cnt[l], 1);
    }
    __syncthreads();

    // counts -> global (integer atomics, order-exact)
    if (chalf == 0 && tid < NUM_CLASSES)
        atomicAdd(&g_cnt[tsel][tid], cnt[tid]);

    // ---- register accumulators: class 16k+wid, channels lane+{0,32,64,96} ----
    float4 acc[10];
#pragma unroll
    for (int k = 0; k < 10; ++k) acc[k] = make_float4(0.f, 0.f, 0.f, 0.f);

    // ---- register prefetch of tile 0 ----
    float4 r[2];
    int mylbl;
    {
#pragma unroll
        for (int i = 0; i < 2; ++i) {
            int q = tid + TPB * i;
            int ch = q >> 3, p4 = q & 7;
            r[i] = *(const float4*)(F + (size_t)ch * NPIX + pbase + p4 * 4);
        }
        mylbl = lbl_s[lane];
    }

    for (int t = 0; t < ntiles; ++t) {
        float* tb = tiles + (t & 1) * TILE_W;

        // ---- stage: bank-perfect scalar stores ----
#pragma unroll
        for (int i = 0; i < 2; ++i) {
            int q = tid + TPB * i;
            int ch = q >> 3, p4 = q & 7;
            float* d = tb + ch * TSTRIDE + p4 * 4;
            d[0] = r[i].x; d[1] = r[i].y; d[2] = r[i].z; d[3] = r[i].w;
        }
        const int lblcur = mylbl;
        __syncthreads();   // one barrier per tile (double buffer -> safe)

        // ---- prefetch next tile (label from smem: short latency) ----
        if (t + 1 < ntiles) {
            const int p0 = pbase + (t + 1) * TPX;
#pragma unroll
            for (int i = 0; i < 2; ++i) {
                int q = tid + TPB * i;
                int ch = q >> 3, p4 = q & 7;
                r[i] = *(const float4*)(F + (size_t)ch * NPIX + p0 + p4 * 4);
            }
            mylbl = lbl_s[(t + 1) * TPX + lane];
        }

        // ---- accumulate into registers: warp-uniform class switch ----
        unsigned m = __ballot_sync(0xffffffffu, (lblcur & 15) == wid);
        while (m) {
            const int j = __ffs(m) - 1;
            m &= m - 1;
            const int row = __shfl_sync(0xffffffffu, lblcur, j);
            const float* srcc = tb + lane * TSTRIDE + j;   // bank = lane+j
            const float v0 = srcc[0];
            const float v1 = srcc[32 * TSTRIDE];
            const float v2 = srcc[64 * TSTRIDE];
            const float v3 = srcc[96 * TSTRIDE];
            switch (row >> 4) {        // warp-uniform branch
                ACC_CASE(0) ACC_CASE(1) ACC_CASE(2) ACC_CASE(3) ACC_CASE(4)
                ACC_CASE(5) ACC_CASE(6) ACC_CASE(7) ACC_CASE(8) ACC_CASE(9)
            }
        }
    }

    // ---- epilogue: registers -> global sums via coalesced float REDG ----
    const int nk = (wid < 6) ? 10 : 9;   // classes 16k+wid <= 149
#pragma unroll
    for (int k = 0; k < 10; ++k) {
        if (k < nk) {
            const int cls = 16 * k + wid;
            float* o = &g_sums[tsel][cls][chalf * HCH];
            atomicAdd(o + lane,      acc[k].x);
            atomicAdd(o + lane + 32, acc[k].y);
            atomicAdd(o + lane + 64, acc[k].z);
            atomicAdd(o + lane + 96, acc[k].w);
        }
    }
}

// ---- tail: grid 150 x 256 — read g_sums/g_cnt, norm, then reset state ----
__global__ void reduce_kernel(float* out) {
    const int cls = blockIdx.x;
    const int ch  = threadIdx.x;

    const float ss = g_sums[0][cls][ch];
    const float st = g_sums[1][cls][ch];
    const float cs  = (float)g_cnt[0][cls];
    const float ctn = (float)g_cnt[1][cls];

    const float d = ss / (cs + 1e-8f) - st / (ctn + 1e-8f);

    __shared__ float red[CH];
    __shared__ unsigned int is_last;
    red[ch] = d * d;
    __syncthreads();
#pragma unroll
    for (int s = CH / 2; s > 0; s >>= 1) {
        if (ch < s) red[ch] += red[ch + s];
        __syncthreads();
    }

    // reset for next graph replay (all reads above are complete)
    g_sums[0][cls][ch] = 0.0f;
    g_sums[1][cls][ch] = 0.0f;
    if (ch == 0) {
        g_cnt[0][cls] = 0;
        g_cnt[1][cls] = 0;
        g_csq[cls] = red[0];
        __threadfence();
        unsigned int t = atomicAdd(&g_ticket, 1u);
        is_last = (t == (unsigned)gridDim.x - 1u) ? 1u : 0u;
    }
    __syncthreads();

    if (is_last && ch < 32) {
        float s2 = 0.0f;
#pragma unroll
        for (int i = ch; i < NUM_CLASSES; i += 32)
            s2 += __ldcg(&g_csq[i]);
#pragma unroll
        for (int o = 16; o > 0; o >>= 1)
            s2 += __shfl_down_sync(0xffffffffu, s2, o);
        if (ch == 0) {
            out[0] = sqrtf(s2);
            g_ticket = 0;              // reset for next graph replay
        }
    }
}

extern "C" void kernel_launch(void* const* d_in, const int* in_sizes, int n_in,
                              void* d_out, int out_size) {
    const float* src = (const float*)d_in[0];   // src_fea  [1,256,512,512] f32
    const float* trg = (const float*)d_in[1];   // trg_fea
    const int*   sl  = (const int*)d_in[2];     // src_labels [1,512,512] i32
    const int*   tl  = (const int*)d_in[3];     // trg_pseudo_labels
    float* out = (float*)d_out;

    cudaFuncSetAttribute(accum_kernel,
                         cudaFuncAttributeMaxDynamicSharedMemorySize,
                         SMEM_BYTES);

    dim3 grid(CHUNKS, 2, 2);   // 296 CTAs = one wave at occ 2
    accum_kernel<<<grid, TPB, SMEM_BYTES>>>(src, trg, sl, tl);
    reduce_kernel<<<NUM_CLASSES, CH>>>(out);
}